// round 17
// baseline (speedup 1.0000x reference)
#include <cuda_runtime.h>

#define B_  4
#define L_  4096
#define H_  16
#define D_  128
#define C_  64
#define NC_ 64
#define GATING_Cf 8.0f

// Scratch (allocation-free rule: __device__ globals) — R10 layouts
__device__ float g_final_h[B_ * NC_ * H_ * 2 * D_];   // (b,nc,h,s,d)
__device__ float g_total_A[B_ * NC_ * H_ * 4];        // (b,nc,h,{a00,a01,a10,a11})
__device__ float g_u[B_ * NC_ * H_ * C_ * 2];         // (b,nc,h,t,{u0,u1})
__device__ float g_c[B_ * NC_ * H_ * C_ * 2];         // (b,nc,h,t,{c0,c1})

// ---- f32x2 packed-math helpers (FFMA2: PTX-only on sm_103a) ----
typedef unsigned long long u64t;
__device__ __forceinline__ u64t pk2(float lo, float hi) {
    u64t r; asm("mov.b64 %0,{%1,%2};" : "=l"(r) : "f"(lo), "f"(hi)); return r;
}
__device__ __forceinline__ float2 up2(u64t v) {
    float2 f; asm("mov.b64 {%0,%1},%2;" : "=f"(f.x), "=f"(f.y) : "l"(v)); return f;
}
__device__ __forceinline__ u64t ffma2(u64t a, u64t b, u64t c) {
    u64t d; asm("fma.rn.f32x2 %0,%1,%2,%3;" : "=l"(d) : "l"(a), "l"(b), "l"(c)); return d;
}
__device__ __forceinline__ u64t fmul2(u64t a, u64t b) {
    u64t d; asm("mul.rn.f32x2 %0,%1,%2;" : "=l"(d) : "l"(a), "l"(b)); return d;
}

// ---------------------------------------------------------------------------
// K1: intra-chunk scan, TWO independent chunks (heads) per warp for ILP.
// Block = 128 thr = 4 warps = 8 heads of one (b,nc). Grid = B*NC*2.
// Inner-loop math and all output layouts identical to the proven R10 kernel.
// ---------------------------------------------------------------------------
__global__ __launch_bounds__(128, 6)
void k_intra(const float* __restrict__ alpha, const float* __restrict__ omega,
             const float* __restrict__ dt,    const float* __restrict__ K,
             const float* __restrict__ V,     const float* __restrict__ beta,
             const float* __restrict__ rg)
{
    __shared__ float4 sA[8 * C_];
    __shared__ float  sC1[8 * C_];
    __shared__ float2 sU[8][C_];

    int blk   = blockIdx.x;          // ((b*NC + nc)*2 + hg)
    int hg    = blk & 1;
    int bn    = blk >> 1;
    int nc    = bn % NC_;
    int b     = bn / NC_;
    int hbase = hg * 8;

    // per-timestep scalars for 8 heads (512 items, 128 threads)
    for (int q = threadIdx.x; q < 8 * C_; q += 128) {
        int wi8 = q >> 6;
        int t   = q & 63;
        int h   = hbase + wi8;
        int l   = nc * C_ + t;
        int idx = (b * L_ + l) * H_ + h;

        float al  = alpha[idx];
        float om  = omega[idx];
        float dtt = dt[idx];
        float be  = beta[idx];
        float r   = rg[idx];

        float tau = 0.5f * dtt;
        float ta  = tau * al;
        float to  = tau * om;
        float opa = 1.0f + ta;
        float oma = 1.0f - ta;
        float to2 = to * to;

        float den   = opa * opa + to2 + 1e-6f;
        float invd  = 1.0f / den;
        float a11   = (opa * oma - to2) * invd;
        float a12   = 2.0f * to * invd;

        float numer = oma * oma + to2;
        float den_e = opa * opa + to2;
        float eig   = numer / (den_e + 1e-6f);
        float expo  = (GATING_Cf * r - 1.0f) * 0.5f;
        float scale = exp2f(expo * __log2f(fmaxf(eig, 1e-8f)));
        a11 *= scale;
        a12 *= scale;

        float v0  = V[idx * 2 + 0];
        float v1  = V[idx * 2 + 1];
        float bdt = be * dtt;

        sA[q]  = make_float4(a11, a12, be, bdt * v0);
        sC1[q] = bdt * v1;
    }
    __syncthreads();

    // c export, R10 layout: 8 heads x 32 float4 = 256 float4
    {
        int basef4 = ((((b * NC_ + nc) * H_ + hbase) * C_) * 2) >> 2;
        for (int q = threadIdx.x; q < 256; q += 128) {
            int hi = q >> 5;
            int t2 = (q & 31) * 2;
            ((float4*)g_c)[basef4 + q] =
                make_float4(sA[hi * C_ + t2].x,     sA[hi * C_ + t2].y,
                            sA[hi * C_ + t2 + 1].x, sA[hi * C_ + t2 + 1].y);
        }
    }

    int wi   = threadIdx.x >> 5;
    int lane = threadIdx.x & 31;
    int cia  = wi * 2;               // chain a head slot
    int cib  = cia + 1;              // chain b head slot
    int ha   = hbase + cia;
    int hb   = hbase + cib;
    bool lo16 = (lane < 16);

    // chain a state
    u64t A0a = 0, A0b = 0, A1a = 0, A1b = 0;
    float AxA = 1.f, AyA = 0.f;
    // chain b state
    u64t B0a = 0, B0b = 0, B1a = 0, B1b = 0;
    float AxB = 1.f, AyB = 0.f;

    const float4* Kpa = (const float4*)K + ((b * L_ + nc * C_) * H_ + ha) * (D_ / 4) + lane;
    const float4* Kpb = (const float4*)K + ((b * L_ + nc * C_) * H_ + hb) * (D_ / 4) + lane;
    const int kstride = H_ * (D_ / 4);

    #pragma unroll 2
    for (int t = 0; t < C_; t++) {
        float4 kva = Kpa[t * kstride];
        float4 kvb = Kpb[t * kstride];
        float4 sca = sA[cia * C_ + t];
        float4 scb = sA[cib * C_ + t];
        float  c1a = sC1[cia * C_ + t];
        float  c1b = sC1[cib * C_ + t];

        u64t ka01 = pk2(kva.x, kva.y);
        u64t ka23 = pk2(kva.z, kva.w);
        u64t kb01 = pk2(kvb.x, kvb.y);
        u64t kb23 = pk2(kvb.z, kvb.w);

        float2 qa0 = up2(ffma2(A0a, ka01, fmul2(A0b, ka23)));
        float2 qa1 = up2(ffma2(A1a, ka01, fmul2(A1b, ka23)));
        float2 qb0 = up2(ffma2(B0a, kb01, fmul2(B0b, kb23)));
        float2 qb1 = up2(ffma2(B1a, kb01, fmul2(B1b, kb23)));
        float pa0 = qa0.x + qa0.y;
        float pa1 = qa1.x + qa1.y;
        float pb0 = qb0.x + qb0.y;
        float pb1 = qb1.x + qb1.y;

        // two independent folded reductions (ILP: chains overlap)
        float xaa = __shfl_xor_sync(0xffffffffu, pa0, 16);
        float xab = __shfl_xor_sync(0xffffffffu, pa1, 16);
        float xba = __shfl_xor_sync(0xffffffffu, pb0, 16);
        float xbb = __shfl_xor_sync(0xffffffffu, pb1, 16);
        float ma = lo16 ? (pa0 + xaa) : (pa1 + xab);
        float mb = lo16 ? (pb0 + xba) : (pb1 + xbb);
        ma += __shfl_xor_sync(0xffffffffu, ma, 8);
        mb += __shfl_xor_sync(0xffffffffu, mb, 8);
        ma += __shfl_xor_sync(0xffffffffu, ma, 4);
        mb += __shfl_xor_sync(0xffffffffu, mb, 4);
        ma += __shfl_xor_sync(0xffffffffu, ma, 2);
        mb += __shfl_xor_sync(0xffffffffu, mb, 2);
        ma += __shfl_xor_sync(0xffffffffu, ma, 1);
        mb += __shfl_xor_sync(0xffffffffu, mb, 1);
        float oa = __shfl_xor_sync(0xffffffffu, ma, 16);
        float ob = __shfl_xor_sync(0xffffffffu, mb, 16);
        float ta0 = lo16 ? ma : oa;
        float ta1 = lo16 ? oa : ma;
        float tb0 = lo16 ? mb : ob;
        float tb1 = lo16 ? ob : mb;

        // chain a: u + state update
        {
            float bd0 = sca.x * ta0 + sca.y * ta1;
            float bd1 = sca.x * ta1 - sca.y * ta0;
            float u0  = sca.w - sca.z * bd0;
            float u1  = c1a  - sca.z * bd1;

            u64t cx2  = pk2(sca.x,  sca.x);
            u64t cy2  = pk2(sca.y,  sca.y);
            u64t ncy2 = pk2(-sca.y, -sca.y);
            u64t u02  = pk2(u0, u0);
            u64t u12  = pk2(u1, u1);

            u64t o0a = A0a, o0b = A0b;
            A0a = ffma2(cx2, A0a, ffma2(cy2, A1a, fmul2(u02, ka01)));
            A0b = ffma2(cx2, A0b, ffma2(cy2, A1b, fmul2(u02, ka23)));
            A1a = ffma2(cx2, A1a, ffma2(ncy2, o0a, fmul2(u12, ka01)));
            A1b = ffma2(cx2, A1b, ffma2(ncy2, o0b, fmul2(u12, ka23)));

            float nAx = sca.x * AxA - sca.y * AyA;
            float nAy = sca.x * AyA + sca.y * AxA;
            AxA = nAx; AyA = nAy;

            if (lane == 0) sU[cia][t] = make_float2(u0, u1);
        }
        // chain b: u + state update
        {
            float bd0 = scb.x * tb0 + scb.y * tb1;
            float bd1 = scb.x * tb1 - scb.y * tb0;
            float u0  = scb.w - scb.z * bd0;
            float u1  = c1b  - scb.z * bd1;

            u64t cx2  = pk2(scb.x,  scb.x);
            u64t cy2  = pk2(scb.y,  scb.y);
            u64t ncy2 = pk2(-scb.y, -scb.y);
            u64t u02  = pk2(u0, u0);
            u64t u12  = pk2(u1, u1);

            u64t o0a = B0a, o0b = B0b;
            B0a = ffma2(cx2, B0a, ffma2(cy2, B1a, fmul2(u02, kb01)));
            B0b = ffma2(cx2, B0b, ffma2(cy2, B1b, fmul2(u02, kb23)));
            B1a = ffma2(cx2, B1a, ffma2(ncy2, o0a, fmul2(u12, kb01)));
            B1b = ffma2(cx2, B1b, ffma2(ncy2, o0b, fmul2(u12, kb23)));

            float nAx = scb.x * AxB - scb.y * AyB;
            float nAy = scb.x * AyB + scb.y * AxB;
            AxB = nAx; AyB = nAy;

            if (lane == 0) sU[cib][t] = make_float2(u0, u1);
        }
    }

    // writebacks (R10 layout, per chain)
    {
        float2 s0a = up2(A0a), s0b = up2(A0b), s1a = up2(A1a), s1b = up2(A1b);
        int base = (((b * NC_ + nc) * H_ + ha) * 2) * D_;
        ((float4*)&g_final_h[base])[lane]      = make_float4(s0a.x, s0a.y, s0b.x, s0b.y);
        ((float4*)&g_final_h[base + D_])[lane] = make_float4(s1a.x, s1a.y, s1b.x, s1b.y);
        if (lane == 0)
            ((float4*)g_total_A)[(b * NC_ + nc) * H_ + ha] = make_float4(AxA, AyA, -AyA, AxA);
    }
    {
        float2 s0a = up2(B0a), s0b = up2(B0b), s1a = up2(B1a), s1b = up2(B1b);
        int base = (((b * NC_ + nc) * H_ + hb) * 2) * D_;
        ((float4*)&g_final_h[base])[lane]      = make_float4(s0a.x, s0a.y, s0b.x, s0b.y);
        ((float4*)&g_final_h[base + D_])[lane] = make_float4(s1a.x, s1a.y, s1b.x, s1b.y);
        if (lane == 0)
            ((float4*)g_total_A)[(b * NC_ + nc) * H_ + hb] = make_float4(AxB, AyB, -AyB, AxB);
    }

    __syncwarp();
    // u writeback: 32 float4 per chain
    {
        float4* uga = (float4*)&g_u[(((b * NC_ + nc) * H_ + ha) * C_) * 2];
        float4* ugb = (float4*)&g_u[(((b * NC_ + nc) * H_ + hb) * C_) * 2];
        uga[lane] = ((const float4*)sU[cia])[lane];
        ugb[lane] = ((const float4*)sU[cib])[lane];
    }
}

// ---------------------------------------------------------------------------
// K2: inter-chunk scan, register-tiled (EXACT R10). Block per (b,h).
// ---------------------------------------------------------------------------
__global__ __launch_bounds__(128)
void k_inter(float* __restrict__ out_states)
{
    __shared__ float4 sA[NC_];

    int b = blockIdx.x >> 4;
    int h = blockIdx.x & 15;
    int d = threadIdx.x;

    if (threadIdx.x < NC_)
        sA[threadIdx.x] = ((const float4*)g_total_A)[(b * NC_ + threadIdx.x) * H_ + h];
    __syncthreads();

    float s0 = 0.f, s1 = 0.f;

    #pragma unroll
    for (int tile = 0; tile < 4; tile++) {
        float f0[16], f1[16];
        #pragma unroll
        for (int i = 0; i < 16; i++) {
            int fb = (((b * NC_ + tile * 16 + i) * H_ + h) * 2) * D_;
            f0[i] = g_final_h[fb + d];
            f1[i] = g_final_h[fb + D_ + d];
        }
        #pragma unroll
        for (int i = 0; i < 16; i++) {
            int nc = tile * 16 + i;
            int ob = (((b * NC_ + nc) * H_ + h) * 2) * D_;
            out_states[ob + d]      = s0;
            out_states[ob + D_ + d] = s1;
            float4 a = sA[nc];
            float ns0 = a.x * s0 + a.y * s1 + f0[i];
            float ns1 = a.z * s0 + a.w * s1 + f1[i];
            s0 = ns0; s1 = ns1;
        }
    }
}

// ---------------------------------------------------------------------------
// K3: output pass (EXACT R10). u/c from exports; fp32 K re-read.
// ---------------------------------------------------------------------------
__global__ __launch_bounds__(256, 7)
void k_full(const float* __restrict__ K, const float* __restrict__ states,
            float* __restrict__ Y)
{
    __shared__ float2 sC[4 * C_];
    __shared__ float2 sU[4 * C_];

    int blk   = blockIdx.x;          // ((b*NC + nc)*4 + hg)
    int hg    = blk & 3;
    int bn    = blk >> 2;
    int nc    = bn % NC_;
    int b     = bn / NC_;
    int hbase = hg * 4;

    if (threadIdx.x < 128) {
        const float4* ug = (const float4*)&g_u[(((b * NC_ + nc) * H_ + hbase) * C_) * 2];
        float4 v = ug[threadIdx.x];
        int hi = threadIdx.x >> 5;
        int t2 = (threadIdx.x & 31) * 2;
        sU[hi * C_ + t2]     = make_float2(v.x, v.y);
        sU[hi * C_ + t2 + 1] = make_float2(v.z, v.w);
    } else {
        int q = threadIdx.x - 128;
        const float4* cg = (const float4*)&g_c[(((b * NC_ + nc) * H_ + hbase) * C_) * 2];
        float4 v = cg[q];
        int hi = q >> 5;
        int t2 = (q & 31) * 2;
        sC[hi * C_ + t2]     = make_float2(v.x, v.y);
        sC[hi * C_ + t2 + 1] = make_float2(v.z, v.w);
    }
    __syncthreads();

    int w    = threadIdx.x >> 5;
    int lane = threadIdx.x & 31;
    int hi   = w >> 1;
    int h    = hbase + hi;
    int dh   = (w & 1) * 64;
    int ci   = hi * C_;

    int sb = (((b * NC_ + nc) * H_ + h) * 2) * D_ + dh + lane * 2;
    float2 z0 = *(const float2*)&states[sb];
    float2 z1 = *(const float2*)&states[sb + D_];

    const float2* Kp2 = (const float2*)(K + ((b * L_ + nc * C_) * H_ + h) * D_ + dh) + lane;
    const int ks2 = H_ * (D_ / 2);
    float2* Yp0 = (float2*)(Y + (((b * L_ + nc * C_) * H_ + h) * 2) * D_ + dh) + lane;
    float2* Yp1 = Yp0 + D_ / 2;
    const int ys2 = H_ * 2 * (D_ / 2);

    #pragma unroll 4
    for (int t = 0; t < C_; t++) {
        float2 kv = __ldcs(&Kp2[t * ks2]);
        float2 c  = sC[ci + t];
        float2 u  = sU[ci + t];

        float o0x = z0.x, o0y = z0.y;
        z0.x = fmaf(c.x, z0.x, fmaf(c.y, z1.x, u.x * kv.x));
        z0.y = fmaf(c.x, z0.y, fmaf(c.y, z1.y, u.x * kv.y));
        z1.x = fmaf(c.x, z1.x, fmaf(-c.y, o0x, u.y * kv.x));
        z1.y = fmaf(c.x, z1.y, fmaf(-c.y, o0y, u.y * kv.y));

        __stcs(&Yp0[t * ys2], z0);
        __stcs(&Yp1[t * ys2], z1);
    }
}

// ---------------------------------------------------------------------------
extern "C" void kernel_launch(void* const* d_in, const int* in_sizes, int n_in,
                              void* d_out, int out_size)
{
    const float* alpha = (const float*)d_in[0];
    const float* omega = (const float*)d_in[1];
    const float* dt    = (const float*)d_in[2];
    const float* K     = (const float*)d_in[3];
    const float* V     = (const float*)d_in[4];
    const float* beta  = (const float*)d_in[5];
    const float* rg    = (const float*)d_in[6];

    float* Y      = (float*)d_out;                       // (B,L,H,2,D)
    float* states = Y + (size_t)B_ * L_ * H_ * 2 * D_;   // (B,NC,H,2,D)

    k_intra<<<B_ * NC_ * 2, 128>>>(alpha, omega, dt, K, V, beta, rg);
    k_inter<<<B_ * H_, 128>>>(states);
    k_full<<<B_ * NC_ * (H_ / 4), 256>>>(K, states, Y);
}